// round 12
// baseline (speedup 1.0000x reference)
#include <cuda_runtime.h>
#include <cuda_bf16.h>
#include <stdint.h>

#define DM   512
#define NH   8
#define HD   64
#define DFF  2048
#define BATCH 2
#define SEQ  4096
#define NR   (BATCH*SEQ)
#define NT   (SEQ/128)

// ---------------- scratch (device globals) ----------------
__device__ __nv_bfloat16 g_Qb[(size_t)BATCH*NH*SEQ*HD];
__device__ __nv_bfloat16 g_Kb[(size_t)BATCH*NH*SEQ*HD];
__device__ __nv_bfloat16 g_Vb[(size_t)BATCH*NH*SEQ*HD];
__device__ float g_C [(size_t)NR*DM];
__device__ float g_Y [(size_t)NR*DM];
__device__ float g_X1[(size_t)NR*DM];
__device__ float g_H [(size_t)NR*DFF];
__device__ unsigned char g_MF[BATCH*32*32];   // per-tile "mask all ones" flags

// ======================= PTX helpers ==================================
__device__ __forceinline__ uint32_t smem_u32(const void* p) {
    uint32_t a;
    asm("{ .reg .u64 t; cvta.to.shared.u64 t, %1; cvt.u32.u64 %0, t; }" : "=r"(a) : "l"(p));
    return a;
}
__device__ __forceinline__ void cpa16(uint32_t dst, const void* src) {
    asm volatile("cp.async.cg.shared.global [%0], [%1], 16;" :: "r"(dst), "l"(src) : "memory");
}
__device__ __forceinline__ void cpa_commit() { asm volatile("cp.async.commit_group;" ::: "memory"); }
__device__ __forceinline__ void cpa_wait0()  { asm volatile("cp.async.wait_group 0;" ::: "memory"); }

__device__ __forceinline__ void ldsm4(uint32_t* r, uint32_t a) {
    asm volatile("ldmatrix.sync.aligned.m8n8.x4.shared.b16 {%0,%1,%2,%3}, [%4];"
        : "=r"(r[0]), "=r"(r[1]), "=r"(r[2]), "=r"(r[3]) : "r"(a));
}
__device__ __forceinline__ void ldsm4t(uint32_t* r, uint32_t a) {
    asm volatile("ldmatrix.sync.aligned.m8n8.x4.trans.shared.b16 {%0,%1,%2,%3}, [%4];"
        : "=r"(r[0]), "=r"(r[1]), "=r"(r[2]), "=r"(r[3]) : "r"(a));
}
__device__ __forceinline__ void hmma(float* d, const uint32_t* a, const uint32_t* b) {
    asm("mma.sync.aligned.m16n8k16.row.col.f32.bf16.bf16.f32 "
        "{%0,%1,%2,%3}, {%4,%5,%6,%7}, {%8,%9}, {%0,%1,%2,%3};"
        : "+f"(d[0]), "+f"(d[1]), "+f"(d[2]), "+f"(d[3])
        : "r"(a[0]), "r"(a[1]), "r"(a[2]), "r"(a[3]), "r"(b[0]), "r"(b[1]));
}
__device__ __forceinline__ void mmatf(float* d, const uint32_t* a, const uint32_t* b) {
    asm("mma.sync.aligned.m16n8k8.row.col.f32.tf32.tf32.f32 "
        "{%0,%1,%2,%3}, {%4,%5,%6,%7}, {%8,%9}, {%0,%1,%2,%3};"
        : "+f"(d[0]), "+f"(d[1]), "+f"(d[2]), "+f"(d[3])
        : "r"(a[0]), "r"(a[1]), "r"(a[2]), "r"(a[3]), "r"(b[0]), "r"(b[1]));
}
__device__ __forceinline__ uint32_t f2tf32(float x) {
    uint32_t r; asm("cvt.rna.tf32.f32 %0, %1;" : "=r"(r) : "f"(x)); return r;
}
__device__ __forceinline__ float ex2f(float x) { float y; asm("ex2.approx.ftz.f32 %0, %1;" : "=f"(y) : "f"(x)); return y; }
__device__ __forceinline__ uint32_t packbf(float lo, float hi) {
    uint32_t r; asm("cvt.rn.bf16x2.f32 %0, %1, %2;" : "=r"(r) : "f"(hi), "f"(lo)); return r;
}

// ======================= mask tile flags ==============================
// one block per 128x128 tile of mask[b]; flag=1 iff every element == 1.0f
__global__ void mask_flags_kernel(const float* __restrict__ mask,
                                  unsigned char* __restrict__ MF)
{
    const int t = blockIdx.x;                 // b*1024 + qt*32 + kt
    const int b = t >> 10, qt = (t >> 5) & 31, kt = t & 31;
    const float* base = mask + (size_t)b * SEQ * SEQ + ((size_t)qt << 7) * SEQ + (kt << 7);
    bool ok = true;
#pragma unroll
    for (int u = 0; u < 16; u++) {
        const int idx = threadIdx.x + (u << 8);   // 0..4095
        const int r = idx >> 5, c = (idx & 31) << 2;
        const float4 v = *(const float4*)(base + (size_t)r * SEQ + c);
        ok = ok && (v.x == 1.f) && (v.y == 1.f) && (v.z == 1.f) && (v.w == 1.f);
    }
    const bool all = __syncthreads_and(ok);
    if (threadIdx.x == 0) MF[t] = all ? 1 : 0;
}

// ======================= tf32 HMMA GEMM body (round-4, proven) ========
// MODE 0: fp32 out [M,N] (+add/relu). MODE 1: bf16 out [bh][s][d].
template<int MODE>
__device__ __forceinline__ void gemm_tf32_body(
    const float* __restrict__ A, const float* __restrict__ Bw,
    const float* __restrict__ bias, const float* __restrict__ add,
    void* __restrict__ Cout, int N, int K, int relu, int bm, int bn)
{
    __shared__ uint32_t As[2][16][136];
    __shared__ uint32_t Bs[2][16][136];

    const int tid = threadIdx.x;
    const int w = tid >> 5, lane = tid & 31;
    const int row0 = tid >> 2;
    const int kq   = (tid & 3) << 2;
    const int wm = (w >> 2) << 6;
    const int wn = (w & 3) << 5;
    const int fr = lane >> 2, fk = lane & 3;

    const float* Ap0 = A  + (size_t)(bm + row0) * K + kq;
    const float* Ap1 = Ap0 + (size_t)64 * K;
    const float* Bp0 = Bw + (size_t)(bn + row0) * K + kq;
    const float* Bp1 = Bp0 + (size_t)64 * K;

    float acc[4][4][4];
#pragma unroll
    for (int i = 0; i < 4; i++)
#pragma unroll
        for (int j = 0; j < 4; j++)
#pragma unroll
            for (int r = 0; r < 4; r++) acc[i][j][r] = 0.f;

    float4 ra0 = *(const float4*)(Ap0);
    float4 ra1 = *(const float4*)(Ap1);
    float4 rb0 = *(const float4*)(Bp0);
    float4 rb1 = *(const float4*)(Bp1);

    const int KT = K >> 4;
    for (int kt = 0; kt < KT; kt++) {
        const int cur = kt & 1;
        const int csw = ((kq >> 2) & 3) << 3;
        {
            const float a0v[4] = {ra0.x, ra0.y, ra0.z, ra0.w};
            const float a1v[4] = {ra1.x, ra1.y, ra1.z, ra1.w};
            const float b0v[4] = {rb0.x, rb0.y, rb0.z, rb0.w};
            const float b1v[4] = {rb1.x, rb1.y, rb1.z, rb1.w};
#pragma unroll
            for (int j = 0; j < 4; j++) {
                const int k = kq + j;
                As[cur][k][row0        ^ csw] = f2tf32(a0v[j]);
                As[cur][k][(row0 + 64) ^ csw] = f2tf32(a1v[j]);
                Bs[cur][k][row0        ^ csw] = f2tf32(b0v[j]);
                Bs[cur][k][(row0 + 64) ^ csw] = f2tf32(b1v[j]);
            }
        }
        __syncthreads();

        if (kt + 1 < KT) {
            const int off = (kt + 1) << 4;
            ra0 = *(const float4*)(Ap0 + off);
            ra1 = *(const float4*)(Ap1 + off);
            rb0 = *(const float4*)(Bp0 + off);
            rb1 = *(const float4*)(Bp1 + off);
        }

#pragma unroll
        for (int ks = 0; ks < 2; ks++) {
            const int k0 = (ks << 3) + fk;
            const int k1 = k0 + 4;
            const int sw0 = ((k0 >> 2) & 3) << 3;
            const int sw1 = ((k1 >> 2) & 3) << 3;
            uint32_t af[4][4], bf[4][2];
#pragma unroll
            for (int mb = 0; mb < 4; mb++) {
                const int m = wm + (mb << 4) + fr;
                af[mb][0] = As[cur][k0][m       ^ sw0];
                af[mb][1] = As[cur][k0][(m + 8) ^ sw0];
                af[mb][2] = As[cur][k1][m       ^ sw1];
                af[mb][3] = As[cur][k1][(m + 8) ^ sw1];
            }
#pragma unroll
            for (int nb = 0; nb < 4; nb++) {
                const int n = wn + (nb << 3) + fr;
                bf[nb][0] = Bs[cur][k0][n ^ sw0];
                bf[nb][1] = Bs[cur][k1][n ^ sw1];
            }
#pragma unroll
            for (int mb = 0; mb < 4; mb++)
#pragma unroll
                for (int nb = 0; nb < 4; nb++)
                    mmatf(acc[mb][nb], af[mb], bf[nb]);
        }
        __syncthreads();
    }

#pragma unroll
    for (int mb = 0; mb < 4; mb++) {
        const int r0 = bm + wm + (mb << 4) + fr;
        const int r1 = r0 + 8;
#pragma unroll
        for (int nb = 0; nb < 4; nb++) {
            const int gc = bn + wn + (nb << 3) + (fk << 1);
            const float2 b2 = *(const float2*)(bias + gc);
            float2 v0 = make_float2(acc[mb][nb][0] + b2.x, acc[mb][nb][1] + b2.y);
            float2 v1 = make_float2(acc[mb][nb][2] + b2.x, acc[mb][nb][3] + b2.y);
            if (MODE == 0) {
                if (add) {
                    const float2 a0 = *(const float2*)(add + (size_t)r0 * N + gc);
                    const float2 a1 = *(const float2*)(add + (size_t)r1 * N + gc);
                    v0.x += a0.x; v0.y += a0.y; v1.x += a1.x; v1.y += a1.y;
                }
                if (relu) {
                    v0.x = fmaxf(v0.x, 0.f); v0.y = fmaxf(v0.y, 0.f);
                    v1.x = fmaxf(v1.x, 0.f); v1.y = fmaxf(v1.y, 0.f);
                }
                *(float2*)((float*)Cout + (size_t)r0 * N + gc) = v0;
                *(float2*)((float*)Cout + (size_t)r1 * N + gc) = v1;
            } else {
                const int hh = gc >> 6, d = gc & 63;
                __nv_bfloat16* Cb = (__nv_bfloat16*)Cout;
                {
                    const int bb = r0 >> 12, s = r0 & 4095;
                    *(__nv_bfloat162*)(Cb + (((size_t)(bb*NH + hh)*SEQ + s) << 6) + d) =
                        __floats2bfloat162_rn(v0.x, v0.y);
                }
                {
                    const int bb = r1 >> 12, s = r1 & 4095;
                    *(__nv_bfloat162*)(Cb + (((size_t)(bb*NH + hh)*SEQ + s) << 6) + d) =
                        __floats2bfloat162_rn(v1.x, v1.y);
                }
            }
        }
    }
}

template<int MODE>
__global__ __launch_bounds__(256, 2)
void gemm_tf32(const float* __restrict__ A, const float* __restrict__ Bw,
               const float* __restrict__ bias, const float* __restrict__ add,
               void* __restrict__ Cout, int M, int N, int K, int relu)
{
    gemm_tf32_body<MODE>(A, Bw, bias, add, Cout, N, K, relu,
                         (int)(blockIdx.y << 7), (int)(blockIdx.x << 7));
}

// fused QKV: blockIdx.x in [0,12): sel = x>>2 picks W/bias/out, x&3 picks N tile
__global__ __launch_bounds__(256, 2)
void qkv_tf32(const float* __restrict__ A,
              const float* __restrict__ Wq, const float* __restrict__ Wk,
              const float* __restrict__ Wv,
              const float* __restrict__ bq, const float* __restrict__ bk,
              const float* __restrict__ bv,
              __nv_bfloat16* Qp, __nv_bfloat16* Kp, __nv_bfloat16* Vp)
{
    const int sel = blockIdx.x >> 2;
    const float* W    = (sel == 0) ? Wq : (sel == 1) ? Wk : Wv;
    const float* bias = (sel == 0) ? bq : (sel == 1) ? bk : bv;
    __nv_bfloat16* out = (sel == 0) ? Qp : (sel == 1) ? Kp : Vp;
    gemm_tf32_body<1>(A, W, bias, nullptr, out, DM, DM, 0,
                      (int)(blockIdx.y << 7), (int)((blockIdx.x & 3) << 7));
}

// ======================= HMMA flash attention (mask-skip v3) ===========
#define SQ_OFF 0
#define SK_OFF 16384
#define SV_OFF 49152
#define ATT_SMEM 81920

__global__ __launch_bounds__(256, 2)
void attn_hmma_kernel(const __nv_bfloat16* __restrict__ Qb,
                      const __nv_bfloat16* __restrict__ Kb,
                      const __nv_bfloat16* __restrict__ Vb,
                      const float* __restrict__ mask,
                      const unsigned char* __restrict__ MF,
                      float* __restrict__ ctx)
{
    extern __shared__ char smem[];
    const uint32_t sb = smem_u32(smem);
    const uint32_t sQ = sb + SQ_OFF, sK = sb + SK_OFF, sV = sb + SV_OFF;

    const int tid = threadIdx.x, w = tid >> 5, lane = tid & 31;
    const int h = blockIdx.x, qt = blockIdx.y, b = blockIdx.z;
    const int bh = b * NH + h;

    const char* Qg = (const char*)(Qb + ((size_t)bh * SEQ + ((size_t)qt << 7)) * HD);
    const char* Kg = (const char*)(Kb + (size_t)bh * SEQ * HD);
    const char* Vg = (const char*)(Vb + (size_t)bh * SEQ * HD);
    const unsigned char* mfp = MF + (((b << 5) | qt) << 5);

    uint32_t offS[4], offG[4];
#pragma unroll
    for (int u = 0; u < 4; u++) {
        const int idx = tid + (u << 8);
        const int r = idx >> 3, c = idx & 7;
        offG[u] = (uint32_t)(r * 128 + c * 16);
        offS[u] = (uint32_t)(r * 128 + ((c ^ (r & 7)) << 4));
    }

#pragma unroll
    for (int u = 0; u < 4; u++) {
        cpa16(sQ + offS[u], Qg + offG[u]);
        cpa16(sK + offS[u], Kg + offG[u]);
        cpa16(sV + offS[u], Vg + offG[u]);
    }
    cpa_commit();
    cpa_wait0();
    __syncthreads();

    const int l7 = lane & 7, l15 = lane & 15, lh = lane >> 4, lq = lane >> 3;
    const uint32_t koff0 = (uint32_t)(l7 * 128 + ((lq ^ l7) << 4));
    const uint32_t koff1 = (uint32_t)(l7 * 128 + (((lq + 4) ^ l7) << 4));
    uint32_t voff[4];
#pragma unroll
    for (int d2 = 0; d2 < 4; d2++)
        voff[d2] = (uint32_t)(l15 * 128 + (((d2 * 2 + lh) ^ l7) << 4));

    uint32_t Qf[4][4];
#pragma unroll
    for (int kc = 0; kc < 4; kc++) {
        const uint32_t qa = sQ + (uint32_t)((w * 16 + l15) * 128 + (((kc * 2 + lh) ^ l7) << 4));
        ldsm4(Qf[kc], qa);
    }

    const int r0 = (lane >> 2);
    const float* mrow0 = mask + (size_t)b * SEQ * SEQ + (size_t)((qt << 7) + w * 16 + r0) * SEQ;
    const float* mrow1 = mrow0 + (size_t)8 * SEQ;

    float O[8][4];
#pragma unroll
    for (int i = 0; i < 8; i++)
#pragma unroll
        for (int j = 0; j < 4; j++) O[i][j] = 0.f;
    float l0 = 0.f, l1 = 0.f;

    const float C1 = 0.18033688011112042f;
    const float C2 = -1.4426950408889634e9f;

    for (int kt = 0; kt < NT; kt++) {
        if (kt + 1 < NT) {
            const char* Kn = Kg + (size_t)(kt + 1) * 16384;
            const char* Vn = Vg + (size_t)(kt + 1) * 16384;
            const uint32_t dK = sK + ((kt + 1) & 1) * 16384;
            const uint32_t dV = sV + ((kt + 1) & 1) * 16384;
#pragma unroll
            for (int u = 0; u < 4; u++) {
                cpa16(dK + offS[u], Kn + offG[u]);
                cpa16(dV + offS[u], Vn + offG[u]);
            }
        }
        cpa_commit();

        const bool allones = (mfp[kt] != 0);   // uniform per CTA
        const uint32_t kb_base = sK + (kt & 1) * 16384;
        const uint32_t vb_base = sV + (kt & 1) * 16384;

#pragma unroll
        for (int kb = 0; kb < 8; kb++) {
            // ---- mask bias (skipped entirely for all-ones tiles) ----
            float b00 = 0.f, b01 = 0.f, b02 = 0.f, b03 = 0.f;
            float b10 = 0.f, b11 = 0.f, b12 = 0.f, b13 = 0.f;
            if (!allones) {
                const int mc = (kt << 7) + (kb << 4) + ((lane & 3) << 1);
                const float2 ma  = *(const float2*)(mrow0 + mc);
                const float2 mb  = *(const float2*)(mrow0 + mc + 8);
                const float2 mcv = *(const float2*)(mrow1 + mc);
                const float2 md  = *(const float2*)(mrow1 + mc + 8);
                b00 = (1.f - ma.x)  * C2; b01 = (1.f - ma.y)  * C2;
                b02 = (1.f - mcv.x) * C2; b03 = (1.f - mcv.y) * C2;
                b10 = (1.f - mb.x)  * C2; b11 = (1.f - mb.y)  * C2;
                b12 = (1.f - md.x)  * C2; b13 = (1.f - md.y)  * C2;
            }

            // ---- S = Q K^T: four independent 2-deep HMMA chains ----
            const uint32_t kr0 = kb_base + (uint32_t)((2 * kb) << 10);
            const uint32_t kr1 = kr0 + 1024;
            uint32_t kf0[4], kf1[4], kf2[4], kf3[4];
            ldsm4(kf0, kr0 + koff0);
            ldsm4(kf1, kr0 + koff1);
            ldsm4(kf2, kr1 + koff0);
            ldsm4(kf3, kr1 + koff1);
            float s0a[4] = {0.f,0.f,0.f,0.f}, s0b[4] = {0.f,0.f,0.f,0.f};
            float s1a[4] = {0.f,0.f,0.f,0.f}, s1b[4] = {0.f,0.f,0.f,0.f};
            hmma(s0a, Qf[0], kf0 + 0);
            hmma(s0b, Qf[2], kf1 + 0);
            hmma(s1a, Qf[0], kf2 + 0);
            hmma(s1b, Qf[2], kf3 + 0);
            hmma(s0a, Qf[1], kf0 + 2);
            hmma(s0b, Qf[3], kf1 + 2);
            hmma(s1a, Qf[1], kf2 + 2);
            hmma(s1b, Qf[3], kf3 + 2);

            // ---- V fragments before exp phase (MUFU hides smem latency) ----
            const uint32_t vr = vb_base + (uint32_t)(kb << 11);
            uint32_t v0[4], v1[4], v2[4], v3[4];
            ldsm4t(v0, vr + voff[0]);
            ldsm4t(v1, vr + voff[1]);
            ldsm4t(v2, vr + voff[2]);
            ldsm4t(v3, vr + voff[3]);

            // ---- merge + exp ----
            const float p00 = ex2f(fmaf(s0a[0] + s0b[0], C1, b00));
            const float p01 = ex2f(fmaf(s0a[1] + s0b[1], C1, b01));
            const float p02 = ex2f(fmaf(s0a[2] + s0b[2], C1, b02));
            const float p03 = ex2f(fmaf(s0a[3] + s0b[3], C1, b03));
            const float p10 = ex2f(fmaf(s1a[0] + s1b[0], C1, b10));
            const float p11 = ex2f(fmaf(s1a[1] + s1b[1], C1, b11));
            const float p12 = ex2f(fmaf(s1a[2] + s1b[2], C1, b12));
            const float p13 = ex2f(fmaf(s1a[3] + s1b[3], C1, b13));
            l0 += (p00 + p01) + (p10 + p11);
            l1 += (p02 + p03) + (p12 + p13);

            uint32_t a[4];
            a[0] = packbf(p00, p01);
            a[1] = packbf(p02, p03);
            a[2] = packbf(p10, p11);
            a[3] = packbf(p12, p13);

            // ---- O += P V ----
            hmma(O[0], a, v0 + 0); hmma(O[1], a, v0 + 2);
            hmma(O[2], a, v1 + 0); hmma(O[3], a, v1 + 2);
            hmma(O[4], a, v2 + 0); hmma(O[5], a, v2 + 2);
            hmma(O[6], a, v3 + 0); hmma(O[7], a, v3 + 2);
        }

        cpa_wait0();
        __syncthreads();
    }

    l0 += __shfl_xor_sync(0xffffffffu, l0, 1);
    l0 += __shfl_xor_sync(0xffffffffu, l0, 2);
    l1 += __shfl_xor_sync(0xffffffffu, l1, 1);
    l1 += __shfl_xor_sync(0xffffffffu, l1, 2);
    const float inv0 = 1.0f / l0;
    const float inv1 = 1.0f / l1;

    const size_t grow0 = (size_t)(b * SEQ + (qt << 7) + w * 16 + r0);
    float* c0 = ctx + grow0 * DM + (h << 6) + ((lane & 3) << 1);
    float* c1 = c0 + (size_t)8 * DM;
#pragma unroll
    for (int nb = 0; nb < 8; nb++) {
        *(float2*)(c0 + nb * 8) = make_float2(O[nb][0] * inv0, O[nb][1] * inv0);
        *(float2*)(c1 + nb * 8) = make_float2(O[nb][2] * inv1, O[nb][3] * inv1);
    }
}

// ======================= LayerNorm =======================
__global__ void ln_kernel(const float* __restrict__ X, const float* __restrict__ gam,
                          const float* __restrict__ bet, float* __restrict__ out)
{
    __shared__ float red[2][4];
    const int row = blockIdx.x;
    const int tid = threadIdx.x;
    const float4 v = ((const float4*)(X + (size_t)row * DM))[tid];
    float s = v.x + v.y + v.z + v.w;
    float q = v.x*v.x + v.y*v.y + v.z*v.z + v.w*v.w;
#pragma unroll
    for (int off = 16; off > 0; off >>= 1) {
        s += __shfl_xor_sync(0xffffffffu, s, off);
        q += __shfl_xor_sync(0xffffffffu, q, off);
    }
    const int w = tid >> 5;
    if ((tid & 31) == 0) { red[0][w] = s; red[1][w] = q; }
    __syncthreads();
    s = red[0][0] + red[0][1] + red[0][2] + red[0][3];
    q = red[1][0] + red[1][1] + red[1][2] + red[1][3];
    const float mu  = s * (1.0f / 512.0f);
    const float var = q * (1.0f / 512.0f) - mu * mu;
    const float rs  = rsqrtf(var + 1e-5f);
    const float4 g4 = ((const float4*)gam)[tid];
    const float4 b4 = ((const float4*)bet)[tid];
    float4 r;
    r.x = (v.x - mu) * rs * g4.x + b4.x;
    r.y = (v.y - mu) * rs * g4.y + b4.y;
    r.z = (v.z - mu) * rs * g4.z + b4.z;
    r.w = (v.w - mu) * rs * g4.w + b4.w;
    ((float4*)(out + (size_t)row * DM))[tid] = r;
}

// ======================= launch =======================
extern "C" void kernel_launch(void* const* d_in, const int* in_sizes, int n_in,
                              void* d_out, int out_size)
{
    const float* src  = (const float*)d_in[0];
    const float* mask = (const float*)d_in[1];
    const float* Wq = (const float*)d_in[2];  const float* bq = (const float*)d_in[3];
    const float* Wk = (const float*)d_in[4];  const float* bk = (const float*)d_in[5];
    const float* Wv = (const float*)d_in[6];  const float* bv = (const float*)d_in[7];
    const float* Wo = (const float*)d_in[8];  const float* bo = (const float*)d_in[9];
    const float* W1 = (const float*)d_in[10]; const float* b1 = (const float*)d_in[11];
    const float* W2 = (const float*)d_in[12]; const float* b2 = (const float*)d_in[13];
    const float* g1 = (const float*)d_in[14]; const float* be1 = (const float*)d_in[15];
    const float* g2 = (const float*)d_in[16]; const float* be2 = (const float*)d_in[17];

    __nv_bfloat16 *Qp, *Kp, *Vp;
    float *Cp, *Yp, *X1p, *Hp;
    unsigned char* MFp;
    cudaGetSymbolAddress((void**)&Qp,  g_Qb);
    cudaGetSymbolAddress((void**)&Kp,  g_Kb);
    cudaGetSymbolAddress((void**)&Vp,  g_Vb);
    cudaGetSymbolAddress((void**)&Cp,  g_C);
    cudaGetSymbolAddress((void**)&Yp,  g_Y);
    cudaGetSymbolAddress((void**)&X1p, g_X1);
    cudaGetSymbolAddress((void**)&Hp,  g_H);
    cudaGetSymbolAddress((void**)&MFp, g_MF);

    const dim3 blk(256);
    const dim3 gq(DM / 128, NR / 128);      // (4, 64)
    const dim3 gf1(DFF / 128, NR / 128);    // (16, 64)

    // mask tile flags (runs concurrently-safe before attention)
    mask_flags_kernel<<<BATCH * 32 * 32, 256>>>(mask, MFp);

    // fused QKV -> bf16 [bh][s][d]
    qkv_tf32<<<dim3(12, NR / 128), blk>>>(src, Wq, Wk, Wv, bq, bk, bv, Qp, Kp, Vp);

    // HMMA flash attention with mask-skip
    cudaFuncSetAttribute(attn_hmma_kernel, cudaFuncAttributeMaxDynamicSharedMemorySize, ATT_SMEM);
    const dim3 ga(NH, SEQ / 128, BATCH);
    attn_hmma_kernel<<<ga, blk, ATT_SMEM>>>(Qp, Kp, Vp, mask, MFp, Cp);

    // output projection + residual -> LN1
    gemm_tf32<0><<<gq, blk>>>(Cp, Wo, bo, src, Yp, NR, DM, DM, 0);
    ln_kernel<<<NR, 128>>>(Yp, g1, be1, X1p);

    // FFN
    gemm_tf32<0><<<gf1, blk>>>(X1p, W1, b1, nullptr, Hp, NR, DFF, DM, 1);
    gemm_tf32<0><<<gq,  blk>>>(Hp,  W2, b2, X1p,     Yp, NR, DM, DFF, 0);
    ln_kernel<<<NR, 128>>>(Yp, g2, be2, (float*)d_out);
}

// round 13
// speedup vs baseline: 1.0011x; 1.0011x over previous
#include <cuda_runtime.h>
#include <cuda_bf16.h>
#include <stdint.h>

#define DM   512
#define NH   8
#define HD   64
#define DFF  2048
#define BATCH 2
#define SEQ  4096
#define NR   (BATCH*SEQ)
#define NT   (SEQ/128)

// ---------------- scratch (device globals) ----------------
__device__ __nv_bfloat16 g_Qb[(size_t)BATCH*NH*SEQ*HD];
__device__ __nv_bfloat16 g_Kb[(size_t)BATCH*NH*SEQ*HD];
__device__ __nv_bfloat16 g_Vb[(size_t)BATCH*NH*SEQ*HD];
__device__ float g_C [(size_t)NR*DM];
__device__ float g_Y [(size_t)NR*DM];
__device__ float g_X1[(size_t)NR*DM];
__device__ float g_H [(size_t)NR*DFF];
__device__ unsigned char g_MF[BATCH*32*32];   // per-tile "mask all ones" flags

// ======================= PTX helpers ==================================
__device__ __forceinline__ uint32_t smem_u32(const void* p) {
    uint32_t a;
    asm("{ .reg .u64 t; cvta.to.shared.u64 t, %1; cvt.u32.u64 %0, t; }" : "=r"(a) : "l"(p));
    return a;
}
__device__ __forceinline__ void cpa16(uint32_t dst, const void* src) {
    asm volatile("cp.async.cg.shared.global [%0], [%1], 16;" :: "r"(dst), "l"(src) : "memory");
}
__device__ __forceinline__ void cpa_commit() { asm volatile("cp.async.commit_group;" ::: "memory"); }
__device__ __forceinline__ void cpa_wait0()  { asm volatile("cp.async.wait_group 0;" ::: "memory"); }

__device__ __forceinline__ void ldsm4(uint32_t* r, uint32_t a) {
    asm volatile("ldmatrix.sync.aligned.m8n8.x4.shared.b16 {%0,%1,%2,%3}, [%4];"
        : "=r"(r[0]), "=r"(r[1]), "=r"(r[2]), "=r"(r[3]) : "r"(a));
}
__device__ __forceinline__ void ldsm4t(uint32_t* r, uint32_t a) {
    asm volatile("ldmatrix.sync.aligned.m8n8.x4.trans.shared.b16 {%0,%1,%2,%3}, [%4];"
        : "=r"(r[0]), "=r"(r[1]), "=r"(r[2]), "=r"(r[3]) : "r"(a));
}
__device__ __forceinline__ void hmma(float* d, const uint32_t* a, const uint32_t* b) {
    asm("mma.sync.aligned.m16n8k16.row.col.f32.bf16.bf16.f32 "
        "{%0,%1,%2,%3}, {%4,%5,%6,%7}, {%8,%9}, {%0,%1,%2,%3};"
        : "+f"(d[0]), "+f"(d[1]), "+f"(d[2]), "+f"(d[3])
        : "r"(a[0]), "r"(a[1]), "r"(a[2]), "r"(a[3]), "r"(b[0]), "r"(b[1]));
}
__device__ __forceinline__ void mmatf(float* d, const uint32_t* a, const uint32_t* b) {
    asm("mma.sync.aligned.m16n8k8.row.col.f32.tf32.tf32.f32 "
        "{%0,%1,%2,%3}, {%4,%5,%6,%7}, {%8,%9}, {%0,%1,%2,%3};"
        : "+f"(d[0]), "+f"(d[1]), "+f"(d[2]), "+f"(d[3])
        : "r"(a[0]), "r"(a[1]), "r"(a[2]), "r"(a[3]), "r"(b[0]), "r"(b[1]));
}
__device__ __forceinline__ uint32_t f2tf32(float x) {
    uint32_t r; asm("cvt.rna.tf32.f32 %0, %1;" : "=r"(r) : "f"(x)); return r;
}
__device__ __forceinline__ float ex2f(float x) { float y; asm("ex2.approx.ftz.f32 %0, %1;" : "=f"(y) : "f"(x)); return y; }
__device__ __forceinline__ uint32_t packbf(float lo, float hi) {
    uint32_t r; asm("cvt.rn.bf16x2.f32 %0, %1, %2;" : "=r"(r) : "f"(hi), "f"(lo)); return r;
}

// ======================= mask tile flags ==============================
// one block per 128x128 tile of mask[b]; flag=1 iff every element == 1.0f
__global__ void mask_flags_kernel(const float* __restrict__ mask,
                                  unsigned char* __restrict__ MF)
{
    const int t = blockIdx.x;                 // b*1024 + qt*32 + kt
    const int b = t >> 10, qt = (t >> 5) & 31, kt = t & 31;
    const float* base = mask + (size_t)b * SEQ * SEQ + ((size_t)qt << 7) * SEQ + (kt << 7);
    bool ok = true;
#pragma unroll
    for (int u = 0; u < 16; u++) {
        const int idx = threadIdx.x + (u << 8);   // 0..4095
        const int r = idx >> 5, c = (idx & 31) << 2;
        const float4 v = *(const float4*)(base + (size_t)r * SEQ + c);
        ok = ok && (v.x == 1.f) && (v.y == 1.f) && (v.z == 1.f) && (v.w == 1.f);
    }
    const bool all = __syncthreads_and(ok);
    if (threadIdx.x == 0) MF[t] = all ? 1 : 0;
}

// ======================= tf32 HMMA GEMM body (round-4, proven) ========
// MODE 0: fp32 out [M,N] (+add/relu). MODE 1: bf16 out [bh][s][d].
template<int MODE>
__device__ __forceinline__ void gemm_tf32_body(
    const float* __restrict__ A, const float* __restrict__ Bw,
    const float* __restrict__ bias, const float* __restrict__ add,
    void* __restrict__ Cout, int N, int K, int relu, int bm, int bn)
{
    __shared__ uint32_t As[2][16][136];
    __shared__ uint32_t Bs[2][16][136];

    const int tid = threadIdx.x;
    const int w = tid >> 5, lane = tid & 31;
    const int row0 = tid >> 2;
    const int kq   = (tid & 3) << 2;
    const int wm = (w >> 2) << 6;
    const int wn = (w & 3) << 5;
    const int fr = lane >> 2, fk = lane & 3;

    const float* Ap0 = A  + (size_t)(bm + row0) * K + kq;
    const float* Ap1 = Ap0 + (size_t)64 * K;
    const float* Bp0 = Bw + (size_t)(bn + row0) * K + kq;
    const float* Bp1 = Bp0 + (size_t)64 * K;

    float acc[4][4][4];
#pragma unroll
    for (int i = 0; i < 4; i++)
#pragma unroll
        for (int j = 0; j < 4; j++)
#pragma unroll
            for (int r = 0; r < 4; r++) acc[i][j][r] = 0.f;

    float4 ra0 = *(const float4*)(Ap0);
    float4 ra1 = *(const float4*)(Ap1);
    float4 rb0 = *(const float4*)(Bp0);
    float4 rb1 = *(const float4*)(Bp1);

    const int KT = K >> 4;
    for (int kt = 0; kt < KT; kt++) {
        const int cur = kt & 1;
        const int csw = ((kq >> 2) & 3) << 3;
        {
            const float a0v[4] = {ra0.x, ra0.y, ra0.z, ra0.w};
            const float a1v[4] = {ra1.x, ra1.y, ra1.z, ra1.w};
            const float b0v[4] = {rb0.x, rb0.y, rb0.z, rb0.w};
            const float b1v[4] = {rb1.x, rb1.y, rb1.z, rb1.w};
#pragma unroll
            for (int j = 0; j < 4; j++) {
                const int k = kq + j;
                As[cur][k][row0        ^ csw] = f2tf32(a0v[j]);
                As[cur][k][(row0 + 64) ^ csw] = f2tf32(a1v[j]);
                Bs[cur][k][row0        ^ csw] = f2tf32(b0v[j]);
                Bs[cur][k][(row0 + 64) ^ csw] = f2tf32(b1v[j]);
            }
        }
        __syncthreads();

        if (kt + 1 < KT) {
            const int off = (kt + 1) << 4;
            ra0 = *(const float4*)(Ap0 + off);
            ra1 = *(const float4*)(Ap1 + off);
            rb0 = *(const float4*)(Bp0 + off);
            rb1 = *(const float4*)(Bp1 + off);
        }

#pragma unroll
        for (int ks = 0; ks < 2; ks++) {
            const int k0 = (ks << 3) + fk;
            const int k1 = k0 + 4;
            const int sw0 = ((k0 >> 2) & 3) << 3;
            const int sw1 = ((k1 >> 2) & 3) << 3;
            uint32_t af[4][4], bf[4][2];
#pragma unroll
            for (int mb = 0; mb < 4; mb++) {
                const int m = wm + (mb << 4) + fr;
                af[mb][0] = As[cur][k0][m       ^ sw0];
                af[mb][1] = As[cur][k0][(m + 8) ^ sw0];
                af[mb][2] = As[cur][k1][m       ^ sw1];
                af[mb][3] = As[cur][k1][(m + 8) ^ sw1];
            }
#pragma unroll
            for (int nb = 0; nb < 4; nb++) {
                const int n = wn + (nb << 3) + fr;
                bf[nb][0] = Bs[cur][k0][n ^ sw0];
                bf[nb][1] = Bs[cur][k1][n ^ sw1];
            }
#pragma unroll
            for (int mb = 0; mb < 4; mb++)
#pragma unroll
                for (int nb = 0; nb < 4; nb++)
                    mmatf(acc[mb][nb], af[mb], bf[nb]);
        }
        __syncthreads();
    }

#pragma unroll
    for (int mb = 0; mb < 4; mb++) {
        const int r0 = bm + wm + (mb << 4) + fr;
        const int r1 = r0 + 8;
#pragma unroll
        for (int nb = 0; nb < 4; nb++) {
            const int gc = bn + wn + (nb << 3) + (fk << 1);
            const float2 b2 = *(const float2*)(bias + gc);
            float2 v0 = make_float2(acc[mb][nb][0] + b2.x, acc[mb][nb][1] + b2.y);
            float2 v1 = make_float2(acc[mb][nb][2] + b2.x, acc[mb][nb][3] + b2.y);
            if (MODE == 0) {
                if (add) {
                    const float2 a0 = *(const float2*)(add + (size_t)r0 * N + gc);
                    const float2 a1 = *(const float2*)(add + (size_t)r1 * N + gc);
                    v0.x += a0.x; v0.y += a0.y; v1.x += a1.x; v1.y += a1.y;
                }
                if (relu) {
                    v0.x = fmaxf(v0.x, 0.f); v0.y = fmaxf(v0.y, 0.f);
                    v1.x = fmaxf(v1.x, 0.f); v1.y = fmaxf(v1.y, 0.f);
                }
                *(float2*)((float*)Cout + (size_t)r0 * N + gc) = v0;
                *(float2*)((float*)Cout + (size_t)r1 * N + gc) = v1;
            } else {
                const int hh = gc >> 6, d = gc & 63;
                __nv_bfloat16* Cb = (__nv_bfloat16*)Cout;
                {
                    const int bb = r0 >> 12, s = r0 & 4095;
                    *(__nv_bfloat162*)(Cb + (((size_t)(bb*NH + hh)*SEQ + s) << 6) + d) =
                        __floats2bfloat162_rn(v0.x, v0.y);
                }
                {
                    const int bb = r1 >> 12, s = r1 & 4095;
                    *(__nv_bfloat162*)(Cb + (((size_t)(bb*NH + hh)*SEQ + s) << 6) + d) =
                        __floats2bfloat162_rn(v1.x, v1.y);
                }
            }
        }
    }
}

template<int MODE>
__global__ __launch_bounds__(256, 2)
void gemm_tf32(const float* __restrict__ A, const float* __restrict__ Bw,
               const float* __restrict__ bias, const float* __restrict__ add,
               void* __restrict__ Cout, int M, int N, int K, int relu)
{
    gemm_tf32_body<MODE>(A, Bw, bias, add, Cout, N, K, relu,
                         (int)(blockIdx.y << 7), (int)(blockIdx.x << 7));
}

// fused QKV: blockIdx.x in [0,12): sel = x>>2 picks W/bias/out, x&3 picks N tile
__global__ __launch_bounds__(256, 2)
void qkv_tf32(const float* __restrict__ A,
              const float* __restrict__ Wq, const float* __restrict__ Wk,
              const float* __restrict__ Wv,
              const float* __restrict__ bq, const float* __restrict__ bk,
              const float* __restrict__ bv,
              __nv_bfloat16* Qp, __nv_bfloat16* Kp, __nv_bfloat16* Vp)
{
    const int sel = blockIdx.x >> 2;
    const float* W    = (sel == 0) ? Wq : (sel == 1) ? Wk : Wv;
    const float* bias = (sel == 0) ? bq : (sel == 1) ? bk : bv;
    __nv_bfloat16* out = (sel == 0) ? Qp : (sel == 1) ? Kp : Vp;
    gemm_tf32_body<1>(A, W, bias, nullptr, out, DM, DM, 0,
                      (int)(blockIdx.y << 7), (int)((blockIdx.x & 3) << 7));
}

// ======================= HMMA flash attention (mask-skip v3) ===========
#define SQ_OFF 0
#define SK_OFF 16384
#define SV_OFF 49152
#define ATT_SMEM 81920

__global__ __launch_bounds__(256, 2)
void attn_hmma_kernel(const __nv_bfloat16* __restrict__ Qb,
                      const __nv_bfloat16* __restrict__ Kb,
                      const __nv_bfloat16* __restrict__ Vb,
                      const float* __restrict__ mask,
                      const unsigned char* __restrict__ MF,
                      float* __restrict__ ctx)
{
    extern __shared__ char smem[];
    const uint32_t sb = smem_u32(smem);
    const uint32_t sQ = sb + SQ_OFF, sK = sb + SK_OFF, sV = sb + SV_OFF;

    const int tid = threadIdx.x, w = tid >> 5, lane = tid & 31;
    const int h = blockIdx.x, qt = blockIdx.y, b = blockIdx.z;
    const int bh = b * NH + h;

    const char* Qg = (const char*)(Qb + ((size_t)bh * SEQ + ((size_t)qt << 7)) * HD);
    const char* Kg = (const char*)(Kb + (size_t)bh * SEQ * HD);
    const char* Vg = (const char*)(Vb + (size_t)bh * SEQ * HD);
    const unsigned char* mfp = MF + (((b << 5) | qt) << 5);

    uint32_t offS[4], offG[4];
#pragma unroll
    for (int u = 0; u < 4; u++) {
        const int idx = tid + (u << 8);
        const int r = idx >> 3, c = idx & 7;
        offG[u] = (uint32_t)(r * 128 + c * 16);
        offS[u] = (uint32_t)(r * 128 + ((c ^ (r & 7)) << 4));
    }

#pragma unroll
    for (int u = 0; u < 4; u++) {
        cpa16(sQ + offS[u], Qg + offG[u]);
        cpa16(sK + offS[u], Kg + offG[u]);
        cpa16(sV + offS[u], Vg + offG[u]);
    }
    cpa_commit();
    cpa_wait0();
    __syncthreads();

    const int l7 = lane & 7, l15 = lane & 15, lh = lane >> 4, lq = lane >> 3;
    const uint32_t koff0 = (uint32_t)(l7 * 128 + ((lq ^ l7) << 4));
    const uint32_t koff1 = (uint32_t)(l7 * 128 + (((lq + 4) ^ l7) << 4));
    uint32_t voff[4];
#pragma unroll
    for (int d2 = 0; d2 < 4; d2++)
        voff[d2] = (uint32_t)(l15 * 128 + (((d2 * 2 + lh) ^ l7) << 4));

    uint32_t Qf[4][4];
#pragma unroll
    for (int kc = 0; kc < 4; kc++) {
        const uint32_t qa = sQ + (uint32_t)((w * 16 + l15) * 128 + (((kc * 2 + lh) ^ l7) << 4));
        ldsm4(Qf[kc], qa);
    }

    const int r0 = (lane >> 2);
    const float* mrow0 = mask + (size_t)b * SEQ * SEQ + (size_t)((qt << 7) + w * 16 + r0) * SEQ;
    const float* mrow1 = mrow0 + (size_t)8 * SEQ;

    float O[8][4];
#pragma unroll
    for (int i = 0; i < 8; i++)
#pragma unroll
        for (int j = 0; j < 4; j++) O[i][j] = 0.f;
    float l0 = 0.f, l1 = 0.f;

    const float C1 = 0.18033688011112042f;
    const float C2 = -1.4426950408889634e9f;

    for (int kt = 0; kt < NT; kt++) {
        if (kt + 1 < NT) {
            const char* Kn = Kg + (size_t)(kt + 1) * 16384;
            const char* Vn = Vg + (size_t)(kt + 1) * 16384;
            const uint32_t dK = sK + ((kt + 1) & 1) * 16384;
            const uint32_t dV = sV + ((kt + 1) & 1) * 16384;
#pragma unroll
            for (int u = 0; u < 4; u++) {
                cpa16(dK + offS[u], Kn + offG[u]);
                cpa16(dV + offS[u], Vn + offG[u]);
            }
        }
        cpa_commit();

        const bool allones = (mfp[kt] != 0);   // uniform per CTA
        const uint32_t kb_base = sK + (kt & 1) * 16384;
        const uint32_t vb_base = sV + (kt & 1) * 16384;

#pragma unroll
        for (int kb = 0; kb < 8; kb++) {
            // ---- mask bias (skipped entirely for all-ones tiles) ----
            float b00 = 0.f, b01 = 0.f, b02 = 0.f, b03 = 0.f;
            float b10 = 0.f, b11 = 0.f, b12 = 0.f, b13 = 0.f;
            if (!allones) {
                const int mc = (kt << 7) + (kb << 4) + ((lane & 3) << 1);
                const float2 ma  = *(const float2*)(mrow0 + mc);
                const float2 mb  = *(const float2*)(mrow0 + mc + 8);
                const float2 mcv = *(const float2*)(mrow1 + mc);
                const float2 md  = *(const float2*)(mrow1 + mc + 8);
                b00 = (1.f - ma.x)  * C2; b01 = (1.f - ma.y)  * C2;
                b02 = (1.f - mcv.x) * C2; b03 = (1.f - mcv.y) * C2;
                b10 = (1.f - mb.x)  * C2; b11 = (1.f - mb.y)  * C2;
                b12 = (1.f - md.x)  * C2; b13 = (1.f - md.y)  * C2;
            }

            // ---- S = Q K^T: four independent 2-deep HMMA chains ----
            const uint32_t kr0 = kb_base + (uint32_t)((2 * kb) << 10);
            const uint32_t kr1 = kr0 + 1024;
            uint32_t kf0[4], kf1[4], kf2[4], kf3[4];
            ldsm4(kf0, kr0 + koff0);
            ldsm4(kf1, kr0 + koff1);
            ldsm4(kf2, kr1 + koff0);
            ldsm4(kf3, kr1 + koff1);
            float s0a[4] = {0.f,0.f,0.f,0.f}, s0b[4] = {0.f,0.f,0.f,0.f};
            float s1a[4] = {0.f,0.f,0.f,0.f}, s1b[4] = {0.f,0.f,0.f,0.f};
            hmma(s0a, Qf[0], kf0 + 0);
            hmma(s0b, Qf[2], kf1 + 0);
            hmma(s1a, Qf[0], kf2 + 0);
            hmma(s1b, Qf[2], kf3 + 0);
            hmma(s0a, Qf[1], kf0 + 2);
            hmma(s0b, Qf[3], kf1 + 2);
            hmma(s1a, Qf[1], kf2 + 2);
            hmma(s1b, Qf[3], kf3 + 2);

            // ---- V fragments before exp phase (MUFU hides smem latency) ----
            const uint32_t vr = vb_base + (uint32_t)(kb << 11);
            uint32_t v0[4], v1[4], v2[4], v3[4];
            ldsm4t(v0, vr + voff[0]);
            ldsm4t(v1, vr + voff[1]);
            ldsm4t(v2, vr + voff[2]);
            ldsm4t(v3, vr + voff[3]);

            // ---- merge + exp ----
            const float p00 = ex2f(fmaf(s0a[0] + s0b[0], C1, b00));
            const float p01 = ex2f(fmaf(s0a[1] + s0b[1], C1, b01));
            const float p02 = ex2f(fmaf(s0a[2] + s0b[2], C1, b02));
            const float p03 = ex2f(fmaf(s0a[3] + s0b[3], C1, b03));
            const float p10 = ex2f(fmaf(s1a[0] + s1b[0], C1, b10));
            const float p11 = ex2f(fmaf(s1a[1] + s1b[1], C1, b11));
            const float p12 = ex2f(fmaf(s1a[2] + s1b[2], C1, b12));
            const float p13 = ex2f(fmaf(s1a[3] + s1b[3], C1, b13));
            l0 += (p00 + p01) + (p10 + p11);
            l1 += (p02 + p03) + (p12 + p13);

            uint32_t a[4];
            a[0] = packbf(p00, p01);
            a[1] = packbf(p02, p03);
            a[2] = packbf(p10, p11);
            a[3] = packbf(p12, p13);

            // ---- O += P V ----
            hmma(O[0], a, v0 + 0); hmma(O[1], a, v0 + 2);
            hmma(O[2], a, v1 + 0); hmma(O[3], a, v1 + 2);
            hmma(O[4], a, v2 + 0); hmma(O[5], a, v2 + 2);
            hmma(O[6], a, v3 + 0); hmma(O[7], a, v3 + 2);
        }

        cpa_wait0();
        __syncthreads();
    }

    l0 += __shfl_xor_sync(0xffffffffu, l0, 1);
    l0 += __shfl_xor_sync(0xffffffffu, l0, 2);
    l1 += __shfl_xor_sync(0xffffffffu, l1, 1);
    l1 += __shfl_xor_sync(0xffffffffu, l1, 2);
    const float inv0 = 1.0f / l0;
    const float inv1 = 1.0f / l1;

    const size_t grow0 = (size_t)(b * SEQ + (qt << 7) + w * 16 + r0);
    float* c0 = ctx + grow0 * DM + (h << 6) + ((lane & 3) << 1);
    float* c1 = c0 + (size_t)8 * DM;
#pragma unroll
    for (int nb = 0; nb < 8; nb++) {
        *(float2*)(c0 + nb * 8) = make_float2(O[nb][0] * inv0, O[nb][1] * inv0);
        *(float2*)(c1 + nb * 8) = make_float2(O[nb][2] * inv1, O[nb][3] * inv1);
    }
}

// ======================= LayerNorm =======================
__global__ void ln_kernel(const float* __restrict__ X, const float* __restrict__ gam,
                          const float* __restrict__ bet, float* __restrict__ out)
{
    __shared__ float red[2][4];
    const int row = blockIdx.x;
    const int tid = threadIdx.x;
    const float4 v = ((const float4*)(X + (size_t)row * DM))[tid];
    float s = v.x + v.y + v.z + v.w;
    float q = v.x*v.x + v.y*v.y + v.z*v.z + v.w*v.w;
#pragma unroll
    for (int off = 16; off > 0; off >>= 1) {
        s += __shfl_xor_sync(0xffffffffu, s, off);
        q += __shfl_xor_sync(0xffffffffu, q, off);
    }
    const int w = tid >> 5;
    if ((tid & 31) == 0) { red[0][w] = s; red[1][w] = q; }
    __syncthreads();
    s = red[0][0] + red[0][1] + red[0][2] + red[0][3];
    q = red[1][0] + red[1][1] + red[1][2] + red[1][3];
    const float mu  = s * (1.0f / 512.0f);
    const float var = q * (1.0f / 512.0f) - mu * mu;
    const float rs  = rsqrtf(var + 1e-5f);
    const float4 g4 = ((const float4*)gam)[tid];
    const float4 b4 = ((const float4*)bet)[tid];
    float4 r;
    r.x = (v.x - mu) * rs * g4.x + b4.x;
    r.y = (v.y - mu) * rs * g4.y + b4.y;
    r.z = (v.z - mu) * rs * g4.z + b4.z;
    r.w = (v.w - mu) * rs * g4.w + b4.w;
    ((float4*)(out + (size_t)row * DM))[tid] = r;
}

// ======================= launch =======================
extern "C" void kernel_launch(void* const* d_in, const int* in_sizes, int n_in,
                              void* d_out, int out_size)
{
    const float* src  = (const float*)d_in[0];
    const float* mask = (const float*)d_in[1];
    const float* Wq = (const float*)d_in[2];  const float* bq = (const float*)d_in[3];
    const float* Wk = (const float*)d_in[4];  const float* bk = (const float*)d_in[5];
    const float* Wv = (const float*)d_in[6];  const float* bv = (const float*)d_in[7];
    const float* Wo = (const float*)d_in[8];  const float* bo = (const float*)d_in[9];
    const float* W1 = (const float*)d_in[10]; const float* b1 = (const float*)d_in[11];
    const float* W2 = (const float*)d_in[12]; const float* b2 = (const float*)d_in[13];
    const float* g1 = (const float*)d_in[14]; const float* be1 = (const float*)d_in[15];
    const float* g2 = (const float*)d_in[16]; const float* be2 = (const float*)d_in[17];

    __nv_bfloat16 *Qp, *Kp, *Vp;
    float *Cp, *Yp, *X1p, *Hp;
    unsigned char* MFp;
    cudaGetSymbolAddress((void**)&Qp,  g_Qb);
    cudaGetSymbolAddress((void**)&Kp,  g_Kb);
    cudaGetSymbolAddress((void**)&Vp,  g_Vb);
    cudaGetSymbolAddress((void**)&Cp,  g_C);
    cudaGetSymbolAddress((void**)&Yp,  g_Y);
    cudaGetSymbolAddress((void**)&X1p, g_X1);
    cudaGetSymbolAddress((void**)&Hp,  g_H);
    cudaGetSymbolAddress((void**)&MFp, g_MF);

    const dim3 blk(256);
    const dim3 gq(DM / 128, NR / 128);      // (4, 64)
    const dim3 gf1(DFF / 128, NR / 128);    // (16, 64)

    // mask tile flags (runs concurrently-safe before attention)
    mask_flags_kernel<<<BATCH * 32 * 32, 256>>>(mask, MFp);

    // fused QKV -> bf16 [bh][s][d]
    qkv_tf32<<<dim3(12, NR / 128), blk>>>(src, Wq, Wk, Wv, bq, bk, bv, Qp, Kp, Vp);

    // HMMA flash attention with mask-skip
    cudaFuncSetAttribute(attn_hmma_kernel, cudaFuncAttributeMaxDynamicSharedMemorySize, ATT_SMEM);
    const dim3 ga(NH, SEQ / 128, BATCH);
    attn_hmma_kernel<<<ga, blk, ATT_SMEM>>>(Qp, Kp, Vp, mask, MFp, Cp);

    // output projection + residual -> LN1
    gemm_tf32<0><<<gq, blk>>>(Cp, Wo, bo, src, Yp, NR, DM, DM, 0);
    ln_kernel<<<NR, 128>>>(Yp, g1, be1, X1p);

    // FFN
    gemm_tf32<0><<<gf1, blk>>>(X1p, W1, b1, nullptr, Hp, NR, DFF, DM, 1);
    gemm_tf32<0><<<gq,  blk>>>(Hp,  W2, b2, X1p,     Yp, NR, DM, DFF, 0);
    ln_kernel<<<NR, 128>>>(Yp, g2, be2, (float*)d_out);
}